// round 1
// baseline (speedup 1.0000x reference)
#include <cuda_runtime.h>
#include <cstddef>

#define SEQ 1024
#define EMB 1024
#define BATCH 4
#define NH 16
#define DH 64
#define BH (BATCH*NH)

// ---- scratch (no allocations allowed) ----
__device__ float g_Q[(size_t)BATCH * SEQ * EMB];
__device__ float g_K[(size_t)BATCH * SEQ * EMB];
__device__ float g_V[(size_t)BATCH * SEQ * EMB];
__device__ float g_ctx[(size_t)BATCH * SEQ * EMB];
__device__ float g_attn[(size_t)BH * SEQ * SEQ];   // 256 MB

// ============================================================
// NT GEMM: C[M,N] = A[M,K] @ W[N,K]^T + bias[N]
// A row-major (lda=K), W row-major (ldb=K). 128x128x16 tiles, 256 threads.
// M,N multiple of 128; K multiple of 16.
// ============================================================
__global__ __launch_bounds__(256)
void gemm_nt_bias(const float* __restrict__ A, const float* __restrict__ W,
                  const float* __restrict__ bias, float* __restrict__ C,
                  int M, int N, int K)
{
    __shared__ float As[16][128];
    __shared__ float Ws[16][128];

    const int tid = threadIdx.x;
    const int bm = blockIdx.y * 128;
    const int bn = blockIdx.x * 128;
    const int tr = tid >> 4;   // 0..15
    const int tc = tid & 15;   // 0..15

    float acc[8][8];
#pragma unroll
    for (int i = 0; i < 8; i++)
#pragma unroll
        for (int j = 0; j < 8; j++) acc[i][j] = 0.f;

    for (int k0 = 0; k0 < K; k0 += 16) {
#pragma unroll
        for (int it = 0; it < 2; it++) {
            int f = tid + it * 256;          // 0..511
            int row = f >> 2;                // 0..127
            int c4  = (f & 3) * 4;           // 0,4,8,12
            float4 va = *(const float4*)(A + (size_t)(bm + row) * K + k0 + c4);
            As[c4 + 0][row] = va.x; As[c4 + 1][row] = va.y;
            As[c4 + 2][row] = va.z; As[c4 + 3][row] = va.w;
            float4 vw = *(const float4*)(W + (size_t)(bn + row) * K + k0 + c4);
            Ws[c4 + 0][row] = vw.x; Ws[c4 + 1][row] = vw.y;
            Ws[c4 + 2][row] = vw.z; Ws[c4 + 3][row] = vw.w;
        }
        __syncthreads();

#pragma unroll
        for (int kk = 0; kk < 16; kk++) {
            float a[8], b[8];
            float4 a0 = *(const float4*)&As[kk][tr * 8];
            float4 a1 = *(const float4*)&As[kk][tr * 8 + 4];
            float4 b0 = *(const float4*)&Ws[kk][tc * 8];
            float4 b1 = *(const float4*)&Ws[kk][tc * 8 + 4];
            a[0]=a0.x;a[1]=a0.y;a[2]=a0.z;a[3]=a0.w;a[4]=a1.x;a[5]=a1.y;a[6]=a1.z;a[7]=a1.w;
            b[0]=b0.x;b[1]=b0.y;b[2]=b0.z;b[3]=b0.w;b[4]=b1.x;b[5]=b1.y;b[6]=b1.z;b[7]=b1.w;
#pragma unroll
            for (int i = 0; i < 8; i++)
#pragma unroll
                for (int j = 0; j < 8; j++)
                    acc[i][j] = fmaf(a[i], b[j], acc[i][j]);
        }
        __syncthreads();
    }

#pragma unroll
    for (int i = 0; i < 8; i++) {
        int row = bm + tr * 8 + i;
        float* crow = C + (size_t)row * N + bn + tc * 8;
        const float* brow = bias + bn + tc * 8;
        float4 bb0 = *(const float4*)(brow);
        float4 bb1 = *(const float4*)(brow + 4);
        float4 o0, o1;
        o0.x = acc[i][0] + bb0.x; o0.y = acc[i][1] + bb0.y;
        o0.z = acc[i][2] + bb0.z; o0.w = acc[i][3] + bb0.w;
        o1.x = acc[i][4] + bb1.x; o1.y = acc[i][5] + bb1.y;
        o1.z = acc[i][6] + bb1.z; o1.w = acc[i][7] + bb1.w;
        *(float4*)(crow)     = o0;
        *(float4*)(crow + 4) = o1;
    }
}

// ============================================================
// scores[bh,q,k] = (Q_h[q,:] . K_h[k,:]) / 8 ; masked -> -1e9
// per (b,h): M=N=1024, Kdim=64, lda=ldb=EMB. 128x128 tiles.
// ============================================================
__global__ __launch_bounds__(256)
void scores_kernel(const float* __restrict__ Q, const float* __restrict__ Km,
                   const int* __restrict__ mask, float* __restrict__ attn)
{
    const int bh = blockIdx.z;
    const int b = bh >> 4;
    const int h = bh & 15;
    const float* Ab = Q  + (size_t)b * SEQ * EMB + h * DH;
    const float* Bb = Km + (size_t)b * SEQ * EMB + h * DH;

    __shared__ float As[16][128];
    __shared__ float Ws[16][128];

    const int tid = threadIdx.x;
    const int bm = blockIdx.y * 128;
    const int bn = blockIdx.x * 128;
    const int tr = tid >> 4;
    const int tc = tid & 15;

    float acc[8][8];
#pragma unroll
    for (int i = 0; i < 8; i++)
#pragma unroll
        for (int j = 0; j < 8; j++) acc[i][j] = 0.f;

    for (int k0 = 0; k0 < DH; k0 += 16) {
#pragma unroll
        for (int it = 0; it < 2; it++) {
            int f = tid + it * 256;
            int row = f >> 2;
            int c4  = (f & 3) * 4;
            float4 va = *(const float4*)(Ab + (size_t)(bm + row) * EMB + k0 + c4);
            As[c4 + 0][row] = va.x; As[c4 + 1][row] = va.y;
            As[c4 + 2][row] = va.z; As[c4 + 3][row] = va.w;
            float4 vw = *(const float4*)(Bb + (size_t)(bn + row) * EMB + k0 + c4);
            Ws[c4 + 0][row] = vw.x; Ws[c4 + 1][row] = vw.y;
            Ws[c4 + 2][row] = vw.z; Ws[c4 + 3][row] = vw.w;
        }
        __syncthreads();
#pragma unroll
        for (int kk = 0; kk < 16; kk++) {
            float a[8], bb[8];
            float4 a0 = *(const float4*)&As[kk][tr * 8];
            float4 a1 = *(const float4*)&As[kk][tr * 8 + 4];
            float4 b0 = *(const float4*)&Ws[kk][tc * 8];
            float4 b1 = *(const float4*)&Ws[kk][tc * 8 + 4];
            a[0]=a0.x;a[1]=a0.y;a[2]=a0.z;a[3]=a0.w;a[4]=a1.x;a[5]=a1.y;a[6]=a1.z;a[7]=a1.w;
            bb[0]=b0.x;bb[1]=b0.y;bb[2]=b0.z;bb[3]=b0.w;bb[4]=b1.x;bb[5]=b1.y;bb[6]=b1.z;bb[7]=b1.w;
#pragma unroll
            for (int i = 0; i < 8; i++)
#pragma unroll
                for (int j = 0; j < 8; j++)
                    acc[i][j] = fmaf(a[i], bb[j], acc[i][j]);
        }
        __syncthreads();
    }

    float* out = attn + (size_t)bh * SEQ * SEQ;
    const float inv_scale = 0.125f;   // 1/sqrt(64)
#pragma unroll
    for (int i = 0; i < 8; i++) {
        int q = bm + tr * 8 + i;
        const int* mrow = mask + ((size_t)b * SEQ + q) * SEQ + bn + tc * 8;
        float* orow = out + (size_t)q * SEQ + bn + tc * 8;
        int4 m0 = *(const int4*)(mrow);
        int4 m1 = *(const int4*)(mrow + 4);
        float4 o0, o1;
        o0.x = (m0.x == 0) ? -1e9f : acc[i][0] * inv_scale;
        o0.y = (m0.y == 0) ? -1e9f : acc[i][1] * inv_scale;
        o0.z = (m0.z == 0) ? -1e9f : acc[i][2] * inv_scale;
        o0.w = (m0.w == 0) ? -1e9f : acc[i][3] * inv_scale;
        o1.x = (m1.x == 0) ? -1e9f : acc[i][4] * inv_scale;
        o1.y = (m1.y == 0) ? -1e9f : acc[i][5] * inv_scale;
        o1.z = (m1.z == 0) ? -1e9f : acc[i][6] * inv_scale;
        o1.w = (m1.w == 0) ? -1e9f : acc[i][7] * inv_scale;
        *(float4*)(orow)     = o0;
        *(float4*)(orow + 4) = o1;
    }
}

// ============================================================
// In-place row softmax over last dim (1024). One block per row.
// ============================================================
__global__ __launch_bounds__(256)
void softmax_kernel(float* __restrict__ attn)
{
    float* p = attn + (size_t)blockIdx.x * SEQ;
    const int tid = threadIdx.x;
    float4 v = reinterpret_cast<float4*>(p)[tid];

    __shared__ float smax[8];
    __shared__ float ssum[8];

    float m = fmaxf(fmaxf(v.x, v.y), fmaxf(v.z, v.w));
#pragma unroll
    for (int o = 16; o > 0; o >>= 1) m = fmaxf(m, __shfl_xor_sync(0xffffffffu, m, o));
    if ((tid & 31) == 0) smax[tid >> 5] = m;
    __syncthreads();
    float rowmax = smax[0];
#pragma unroll
    for (int i = 1; i < 8; i++) rowmax = fmaxf(rowmax, smax[i]);

    v.x = __expf(v.x - rowmax);
    v.y = __expf(v.y - rowmax);
    v.z = __expf(v.z - rowmax);
    v.w = __expf(v.w - rowmax);

    float s = v.x + v.y + v.z + v.w;
#pragma unroll
    for (int o = 16; o > 0; o >>= 1) s += __shfl_xor_sync(0xffffffffu, s, o);
    if ((tid & 31) == 0) ssum[tid >> 5] = s;
    __syncthreads();
    float rowsum = ssum[0];
#pragma unroll
    for (int i = 1; i < 8; i++) rowsum += ssum[i];

    float inv = 1.0f / rowsum;
    v.x *= inv; v.y *= inv; v.z *= inv; v.w *= inv;
    reinterpret_cast<float4*>(p)[tid] = v;
}

// ============================================================
// attn_avg[b,q,k] = mean_h attn[b,h,q,k]
// ============================================================
__global__ __launch_bounds__(256)
void avg_kernel(const float* __restrict__ attn, float* __restrict__ out2)
{
    const size_t per_b = (size_t)SEQ * SEQ / 4;   // float4 units per batch
    size_t i = (size_t)blockIdx.x * blockDim.x + threadIdx.x;
    if (i >= (size_t)BATCH * per_b) return;
    size_t b = i / per_b;
    size_t r = i % per_b;
    const float4* base = reinterpret_cast<const float4*>(attn) + b * NH * per_b + r;
    float4 acc = make_float4(0.f, 0.f, 0.f, 0.f);
#pragma unroll
    for (int h = 0; h < NH; h++) {
        float4 t = base[(size_t)h * per_b];
        acc.x += t.x; acc.y += t.y; acc.z += t.z; acc.w += t.w;
    }
    const float inv = 1.0f / NH;
    acc.x *= inv; acc.y *= inv; acc.z *= inv; acc.w *= inv;
    reinterpret_cast<float4*>(out2)[b * per_b + r] = acc;
}

// ============================================================
// ctx[b,q,h*64+d] = sum_k attn[bh,q,k] * V[b,k,h*64+d]
// per (b,h): NN GEMM M=1024(q), N=64(d), Kdim=1024. 64x64x32 tiles.
// ============================================================
__global__ __launch_bounds__(256)
void ctx_kernel(const float* __restrict__ attn, const float* __restrict__ V,
                float* __restrict__ ctx)
{
    const int bh = blockIdx.z;
    const int b = bh >> 4;
    const int h = bh & 15;
    const float* Ab = attn + (size_t)bh * SEQ * SEQ;
    const float* Bb = V + (size_t)b * SEQ * EMB + h * DH;

    __shared__ float As[32][64];   // As[k][m]
    __shared__ float Bs[32][64];   // Bs[k][n]

    const int tid = threadIdx.x;
    const int bm = blockIdx.y * 64;
    const int tr = tid >> 4;   // 0..15 -> m
    const int tc = tid & 15;   // 0..15 -> n

    float acc[4][4];
#pragma unroll
    for (int i = 0; i < 4; i++)
#pragma unroll
        for (int j = 0; j < 4; j++) acc[i][j] = 0.f;

    for (int k0 = 0; k0 < SEQ; k0 += 32) {
#pragma unroll
        for (int it = 0; it < 2; it++) {
            int f = tid + it * 256;          // 0..511
            {
                int row = f >> 3;            // 0..63 (m)
                int c4  = (f & 7) * 4;       // 0..28 (k)
                float4 va = *(const float4*)(Ab + (size_t)(bm + row) * SEQ + k0 + c4);
                As[c4 + 0][row] = va.x; As[c4 + 1][row] = va.y;
                As[c4 + 2][row] = va.z; As[c4 + 3][row] = va.w;
            }
            {
                int row = f >> 4;            // 0..31 (k)
                int c4  = (f & 15) * 4;      // 0..60 (n)
                float4 vb = *(const float4*)(Bb + (size_t)(k0 + row) * EMB + c4);
                *(float4*)&Bs[row][c4] = vb;
            }
        }
        __syncthreads();
#pragma unroll
        for (int kk = 0; kk < 32; kk++) {
            float4 a4 = *(const float4*)&As[kk][tr * 4];
            float4 b4 = *(const float4*)&Bs[kk][tc * 4];
            float a[4] = {a4.x, a4.y, a4.z, a4.w};
            float bb[4] = {b4.x, b4.y, b4.z, b4.w};
#pragma unroll
            for (int i = 0; i < 4; i++)
#pragma unroll
                for (int j = 0; j < 4; j++)
                    acc[i][j] = fmaf(a[i], bb[j], acc[i][j]);
        }
        __syncthreads();
    }

#pragma unroll
    for (int i = 0; i < 4; i++) {
        int q = bm + tr * 4 + i;
        float* crow = ctx + ((size_t)b * SEQ + q) * EMB + h * DH + tc * 4;
        float4 o;
        o.x = acc[i][0]; o.y = acc[i][1]; o.z = acc[i][2]; o.w = acc[i][3];
        *(float4*)crow = o;
    }
}

// ============================================================
extern "C" void kernel_launch(void* const* d_in, const int* in_sizes, int n_in,
                              void* d_out, int out_size)
{
    const float* query = (const float*)d_in[0];
    const float* key   = (const float*)d_in[1];
    const float* value = (const float*)d_in[2];
    const int*   mask  = (const int*)  d_in[3];
    const float* Wq = (const float*)d_in[4];
    const float* bq = (const float*)d_in[5];
    const float* Wk = (const float*)d_in[6];
    const float* bk = (const float*)d_in[7];
    const float* Wv = (const float*)d_in[8];
    const float* bv = (const float*)d_in[9];
    const float* Wo = (const float*)d_in[10];
    const float* bo = (const float*)d_in[11];

    float* out      = (float*)d_out;
    float* attn_avg = out + (size_t)BATCH * SEQ * EMB;

    float *Q, *K, *V, *CTX, *ATT;
    cudaGetSymbolAddress((void**)&Q,   g_Q);
    cudaGetSymbolAddress((void**)&K,   g_K);
    cudaGetSymbolAddress((void**)&V,   g_V);
    cudaGetSymbolAddress((void**)&CTX, g_ctx);
    cudaGetSymbolAddress((void**)&ATT, g_attn);

    const int M = BATCH * SEQ;   // 4096

    dim3 gproj(EMB / 128, M / 128);          // (8, 32)
    gemm_nt_bias<<<gproj, 256>>>(query, Wq, bq, Q, M, EMB, EMB);
    gemm_nt_bias<<<gproj, 256>>>(key,   Wk, bk, K, M, EMB, EMB);
    gemm_nt_bias<<<gproj, 256>>>(value, Wv, bv, V, M, EMB, EMB);

    dim3 gsc(SEQ / 128, SEQ / 128, BH);      // (8, 8, 64)
    scores_kernel<<<gsc, 256>>>(Q, K, mask, ATT);

    softmax_kernel<<<BH * SEQ, 256>>>(ATT);

    {
        size_t total = (size_t)BATCH * SEQ * SEQ / 4;
        int blocks = (int)((total + 255) / 256);
        avg_kernel<<<blocks, 256>>>(ATT, attn_avg);
    }

    dim3 gctx(1, SEQ / 64, BH);              // (1, 16, 64)
    ctx_kernel<<<gctx, 256>>>(ATT, V, CTX);

    gemm_nt_bias<<<gproj, 256>>>(CTX, Wo, bo, out, M, EMB, EMB);
}

// round 3
// speedup vs baseline: 1.5081x; 1.5081x over previous
#include <cuda_runtime.h>
#include <cuda_bf16.h>
#include <cstdint>
#include <cstddef>

#define SEQ 1024
#define EMB 1024
#define BATCH 4
#define NH 16
#define DH 64
#define BH (BATCH*NH)
#define SS ((size_t)SEQ*(size_t)SEQ)

// SMEM tile row stride in 32-bit words: 32 bf16 (16 words) + 4 pad words.
// bank(row,w) = (20*row + w) % 32 -> for the 8-row x 4-word fragment access
// pattern of m16n8k16, all 32 lanes hit distinct banks.
#define SKW 20

// ---- scratch (no device allocations allowed) ----
__device__ float g_Q  [(size_t)BATCH*SEQ*EMB];
__device__ float g_K  [(size_t)BATCH*SEQ*EMB];
__device__ float g_V  [(size_t)BATCH*SEQ*EMB];
__device__ float g_Vt [(size_t)BATCH*SEQ*EMB];
__device__ float g_ctx[(size_t)BATCH*SEQ*EMB];
__device__ float g_attn[(size_t)BH*SEQ*SEQ];   // 268 MB

// ============================================================
// warp MMA: d += a * b  (m16n8k16, bf16 in, fp32 acc)
// ============================================================
__device__ __forceinline__ void mma16816(float* c, const uint32_t a[4], const uint32_t b[2]){
    asm volatile("mma.sync.aligned.m16n8k16.row.col.f32.bf16.bf16.f32 "
        "{%0,%1,%2,%3}, {%4,%5,%6,%7}, {%8,%9}, {%0,%1,%2,%3};"
        : "+f"(c[0]), "+f"(c[1]), "+f"(c[2]), "+f"(c[3])
        : "r"(a[0]), "r"(a[1]), "r"(a[2]), "r"(a[3]), "r"(b[0]), "r"(b[1]));
}

// fp32x8 -> bf16 hi/lo packed words (lo captures rounding error of hi)
__device__ __forceinline__ void cvt8w(const float* __restrict__ p, uint4& h, uint4& l){
    float x[8];
    *(float4*)(x)   = *(const float4*)(p);
    *(float4*)(x+4) = *(const float4*)(p + 4);
    uint32_t hw[8], lw[8];
#pragma unroll
    for (int j = 0; j < 8; j++){
        __nv_bfloat16 hb = __float2bfloat16(x[j]);
        float hf = __bfloat162float(hb);
        __nv_bfloat16 lb = __float2bfloat16(x[j] - hf);
        hw[j] = (uint32_t)__bfloat16_as_ushort(hb);
        lw[j] = (uint32_t)__bfloat16_as_ushort(lb);
    }
    h.x = hw[0] | (hw[1] << 16); h.y = hw[2] | (hw[3] << 16);
    h.z = hw[4] | (hw[5] << 16); h.w = hw[6] | (hw[7] << 16);
    l.x = lw[0] | (lw[1] << 16); l.y = lw[2] | (lw[3] << 16);
    l.z = lw[4] | (lw[5] << 16); l.w = lw[6] | (lw[7] << 16);
}

// load ROWS x 32 fp32 tile (row stride ldg) -> hi/lo bf16 SMEM planes. 256 threads.
template<int ROWS>
__device__ __forceinline__ void load_conv(const float* __restrict__ g, int ldg,
                                          uint32_t* __restrict__ sh, uint32_t* __restrict__ sl,
                                          int tid)
{
#pragma unroll
    for (int i = 0; i < ROWS/64; i++){
        int idx = tid + i*256;
        int row = idx >> 2, s = idx & 3;
        const float* p = g + (size_t)row*ldg + s*8;
        uint4 h, l;
        cvt8w(p, h, l);
        int wb = row*SKW + s*4;
        *(uint4*)(sh + wb) = h;
        *(uint4*)(sl + wb) = l;
    }
}

// one BK=32 chunk of bf16x3 MMAs. MT m-tiles (16 rows), NT n-tiles (8 cols).
template<int MT, int NT>
__device__ __forceinline__ void mma_chunk(float acc[MT][NT][4],
    const uint32_t* __restrict__ sAh, const uint32_t* __restrict__ sAl,
    const uint32_t* __restrict__ sBh, const uint32_t* __restrict__ sBl,
    int mof, int nof, int lane)
{
    const int r = lane >> 2, w = lane & 3;
#pragma unroll
    for (int ks = 0; ks < 2; ks++){
        const int kw = ks*8 + w;
        uint32_t ah[MT][4], al[MT][4], bh[NT][2], bl[NT][2];
#pragma unroll
        for (int mi = 0; mi < MT; mi++){
            int base = (mof + mi*16 + r)*SKW + kw;
            ah[mi][0] = sAh[base];          ah[mi][1] = sAh[base + 8*SKW];
            ah[mi][2] = sAh[base + 4];      ah[mi][3] = sAh[base + 8*SKW + 4];
            al[mi][0] = sAl[base];          al[mi][1] = sAl[base + 8*SKW];
            al[mi][2] = sAl[base + 4];      al[mi][3] = sAl[base + 8*SKW + 4];
        }
#pragma unroll
        for (int ni = 0; ni < NT; ni++){
            int base = (nof + ni*8 + r)*SKW + kw;
            bh[ni][0] = sBh[base];  bh[ni][1] = sBh[base + 4];
            bl[ni][0] = sBl[base];  bl[ni][1] = sBl[base + 4];
        }
#pragma unroll
        for (int mi = 0; mi < MT; mi++)
#pragma unroll
            for (int ni = 0; ni < NT; ni++){
                mma16816(acc[mi][ni], ah[mi], bh[ni]);
                mma16816(acc[mi][ni], ah[mi], bl[ni]);
                mma16816(acc[mi][ni], al[mi], bh[ni]);
            }
    }
}

// ============================================================
// NT GEMM: C[M,N] = A[M,K] @ W[N,K]^T + bias[N]
// CTA 128x128, 8 warps (2m x 4n), warp tile 64x32.
// ============================================================
__global__ __launch_bounds__(256, 1)
void gemm_proj(const float* __restrict__ A, const float* __restrict__ W,
               const float* __restrict__ bias, float* __restrict__ C,
               int M, int N, int K)
{
    __shared__ uint32_t sAh[128*SKW], sAl[128*SKW], sBh[128*SKW], sBl[128*SKW];
    const int tid = threadIdx.x, wid = tid >> 5, lane = tid & 31;
    const int wm = (wid >> 2)*64, wn = (wid & 3)*32;
    const int bm = blockIdx.y*128, bn = blockIdx.x*128;

    float acc[4][4][4];
#pragma unroll
    for (int i = 0; i < 4; i++)
#pragma unroll
        for (int j = 0; j < 4; j++)
#pragma unroll
            for (int k = 0; k < 4; k++) acc[i][j][k] = 0.f;

    const int nch = K >> 5;
    for (int c = 0; c < nch; c++){
        __syncthreads();
        load_conv<128>(A + (size_t)bm*K + c*32, K, sAh, sAl, tid);
        load_conv<128>(W + (size_t)bn*K + c*32, K, sBh, sBl, tid);
        __syncthreads();
        mma_chunk<4,4>(acc, sAh, sAl, sBh, sBl, wm, wn, lane);
    }

    const int r = lane >> 2, cl = (lane & 3)*2;
#pragma unroll
    for (int mi = 0; mi < 4; mi++){
#pragma unroll
        for (int ni = 0; ni < 4; ni++){
            int row = bm + wm + mi*16 + r;
            int col = bn + wn + ni*8 + cl;
            float2 bv = *(const float2*)(bias + col);
            float2 o0, o1;
            o0.x = acc[mi][ni][0] + bv.x; o0.y = acc[mi][ni][1] + bv.y;
            o1.x = acc[mi][ni][2] + bv.x; o1.y = acc[mi][ni][3] + bv.y;
            *(float2*)(C + (size_t)row*N + col)     = o0;
            *(float2*)(C + (size_t)(row+8)*N + col) = o1;
        }
    }
}

// ============================================================
// scores[bh,q,k] = (Q_h[q,:].K_h[k,:])/8, masked -> -1e9. Kdim=64.
// ============================================================
__global__ __launch_bounds__(256, 1)
void scores_mma(const float* __restrict__ Q, const float* __restrict__ Km,
                const int* __restrict__ mask, float* __restrict__ attn)
{
    __shared__ uint32_t sAh[128*SKW], sAl[128*SKW], sBh[128*SKW], sBl[128*SKW];
    const int tid = threadIdx.x, wid = tid >> 5, lane = tid & 31;
    const int wm = (wid >> 2)*64, wn = (wid & 3)*32;
    const int bh = blockIdx.z, b = bh >> 4, h = bh & 15;
    const int bm = blockIdx.y*128, bn = blockIdx.x*128;
    const float* Ab = Q  + ((size_t)b*SEQ + bm)*EMB + h*DH;
    const float* Bb = Km + ((size_t)b*SEQ + bn)*EMB + h*DH;

    float acc[4][4][4];
#pragma unroll
    for (int i = 0; i < 4; i++)
#pragma unroll
        for (int j = 0; j < 4; j++)
#pragma unroll
            for (int k = 0; k < 4; k++) acc[i][j][k] = 0.f;

#pragma unroll
    for (int c = 0; c < 2; c++){
        __syncthreads();
        load_conv<128>(Ab + c*32, EMB, sAh, sAl, tid);
        load_conv<128>(Bb + c*32, EMB, sBh, sBl, tid);
        __syncthreads();
        mma_chunk<4,4>(acc, sAh, sAl, sBh, sBl, wm, wn, lane);
    }

    const int r = lane >> 2, cl = (lane & 3)*2;
    float* out = attn + (size_t)bh*SS;
#pragma unroll
    for (int mi = 0; mi < 4; mi++){
#pragma unroll
        for (int ni = 0; ni < 4; ni++){
            int row = bm + wm + mi*16 + r;
            int col = bn + wn + ni*8 + cl;
#pragma unroll
            for (int half = 0; half < 2; half++){
                int q = row + half*8;
                int2 m = *(const int2*)(mask + ((size_t)b*SEQ + q)*SEQ + col);
                float2 o;
                o.x = (m.x == 0) ? -1e9f : acc[mi][ni][half*2+0]*0.125f;
                o.y = (m.y == 0) ? -1e9f : acc[mi][ni][half*2+1]*0.125f;
                *(float2*)(out + (size_t)q*SEQ + col) = o;
            }
        }
    }
}

// ============================================================
// ctx = attn @ V (via Vt).  CTA 128x64, warps 2m x 4n, warp tile 64x16.
// ============================================================
__global__ __launch_bounds__(256, 1)
void ctx_mma(const float* __restrict__ attn, const float* __restrict__ Vt,
             float* __restrict__ ctx)
{
    __shared__ uint32_t sAh[128*SKW], sAl[128*SKW], sBh[64*SKW], sBl[64*SKW];
    const int tid = threadIdx.x, wid = tid >> 5, lane = tid & 31;
    const int wm = (wid >> 2)*64, wn = (wid & 3)*16;
    const int bh = blockIdx.y, b = bh >> 4, h = bh & 15;
    const int bm = blockIdx.x*128;
    const float* Ab = attn + (size_t)bh*SS + (size_t)bm*SEQ;
    const float* Bb = Vt + (size_t)b*SEQ*EMB + (size_t)(h*DH)*SEQ;

    float acc[4][2][4];
#pragma unroll
    for (int i = 0; i < 4; i++)
#pragma unroll
        for (int j = 0; j < 2; j++)
#pragma unroll
            for (int k = 0; k < 4; k++) acc[i][j][k] = 0.f;

    for (int c = 0; c < 32; c++){
        __syncthreads();
        load_conv<128>(Ab + c*32, SEQ, sAh, sAl, tid);
        load_conv<64> (Bb + c*32, SEQ, sBh, sBl, tid);
        __syncthreads();
        mma_chunk<4,2>(acc, sAh, sAl, sBh, sBl, wm, wn, lane);
    }

    const int r = lane >> 2, cl = (lane & 3)*2;
#pragma unroll
    for (int mi = 0; mi < 4; mi++){
#pragma unroll
        for (int ni = 0; ni < 2; ni++){
            int row = bm + wm + mi*16 + r;
            int col = wn + ni*8 + cl;
            float* base = ctx + ((size_t)b*SEQ + row)*EMB + h*DH + col;
            float2 o0, o1;
            o0.x = acc[mi][ni][0]; o0.y = acc[mi][ni][1];
            o1.x = acc[mi][ni][2]; o1.y = acc[mi][ni][3];
            *(float2*)(base)          = o0;
            *(float2*)(base + 8*EMB)  = o1;
        }
    }
}

// ============================================================
// V transpose per batch: Vt[b][e][s] = V[b][s][e]
// ============================================================
__global__ void transpose_k(const float* __restrict__ V, float* __restrict__ Vt)
{
    __shared__ float tile[32][33];
    const int b = blockIdx.z;
    const int e0 = blockIdx.x*32, s0 = blockIdx.y*32;
    const int tx = threadIdx.x, ty = threadIdx.y;
    const float* src = V + (size_t)b*SEQ*EMB;
    float* dst = Vt + (size_t)b*SEQ*EMB;
#pragma unroll
    for (int i = 0; i < 32; i += 8)
        tile[ty + i][tx] = src[(size_t)(s0 + ty + i)*EMB + e0 + tx];
    __syncthreads();
#pragma unroll
    for (int i = 0; i < 32; i += 8)
        dst[(size_t)(e0 + ty + i)*SEQ + s0 + tx] = tile[tx][ty + i];
}

// ============================================================
// fused in-place softmax + head-average. CTA per (b,q).
// thread t: head h = t>>4, 64-col segment part = t&15.
// ============================================================
#define SM_SOFT (256*68*4)

__global__ __launch_bounds__(256)
void softmax_avg(float* __restrict__ attn, float* __restrict__ avg)
{
    extern __shared__ float sp[];
    const int bq = blockIdx.x, b = bq >> 10, q = bq & 1023;
    const int t = threadIdx.x, h = t >> 4, part = t & 15;
    float* row = attn + ((size_t)(b*NH + h)*SEQ + q)*SEQ + part*64;

    float4 v[16];
    float m = -3.0e38f;
#pragma unroll
    for (int i = 0; i < 16; i++){
        v[i] = ((const float4*)row)[i];
        m = fmaxf(m, fmaxf(fmaxf(v[i].x, v[i].y), fmaxf(v[i].z, v[i].w)));
    }
#pragma unroll
    for (int o = 8; o; o >>= 1) m = fmaxf(m, __shfl_xor_sync(0xffffffffu, m, o));

    float ssum = 0.f;
#pragma unroll
    for (int i = 0; i < 16; i++){
        v[i].x = __expf(v[i].x - m); v[i].y = __expf(v[i].y - m);
        v[i].z = __expf(v[i].z - m); v[i].w = __expf(v[i].w - m);
        ssum += v[i].x + v[i].y + v[i].z + v[i].w;
    }
#pragma unroll
    for (int o = 8; o; o >>= 1) ssum += __shfl_xor_sync(0xffffffffu, ssum, o);

    const float inv = 1.0f / ssum;
    float* slot = sp + (h*16 + part)*68;
#pragma unroll
    for (int i = 0; i < 16; i++){
        v[i].x *= inv; v[i].y *= inv; v[i].z *= inv; v[i].w *= inv;
        ((float4*)row)[i] = v[i];
        *(float4*)(slot + i*4) = v[i];
    }
    __syncthreads();

    const int part2 = t >> 4, j = t & 15;
    float4 a4 = make_float4(0.f, 0.f, 0.f, 0.f);
#pragma unroll
    for (int hh = 0; hh < 16; hh++){
        float4 p = *(const float4*)(sp + (hh*16 + part2)*68 + j*4);
        a4.x += p.x; a4.y += p.y; a4.z += p.z; a4.w += p.w;
    }
    a4.x *= 0.0625f; a4.y *= 0.0625f; a4.z *= 0.0625f; a4.w *= 0.0625f;
    *(float4*)(avg + ((size_t)b*SEQ + q)*SEQ + t*4) = a4;
}

// ============================================================
extern "C" void kernel_launch(void* const* d_in, const int* in_sizes, int n_in,
                              void* d_out, int out_size)
{
    const float* query = (const float*)d_in[0];
    const float* key   = (const float*)d_in[1];
    const float* value = (const float*)d_in[2];
    const int*   mask  = (const int*)  d_in[3];
    const float* Wq = (const float*)d_in[4];
    const float* bq = (const float*)d_in[5];
    const float* Wk = (const float*)d_in[6];
    const float* bk = (const float*)d_in[7];
    const float* Wv = (const float*)d_in[8];
    const float* bv = (const float*)d_in[9];
    const float* Wo = (const float*)d_in[10];
    const float* bo = (const float*)d_in[11];

    float* out      = (float*)d_out;
    float* attn_avg = out + (size_t)BATCH*SEQ*EMB;

    float *Q, *K, *V, *VT, *CTX, *ATT;
    cudaGetSymbolAddress((void**)&Q,   g_Q);
    cudaGetSymbolAddress((void**)&K,   g_K);
    cudaGetSymbolAddress((void**)&V,   g_V);
    cudaGetSymbolAddress((void**)&VT,  g_Vt);
    cudaGetSymbolAddress((void**)&CTX, g_ctx);
    cudaGetSymbolAddress((void**)&ATT, g_attn);

    cudaFuncSetAttribute(softmax_avg, cudaFuncAttributeMaxDynamicSharedMemorySize, SM_SOFT);

    const int M = BATCH*SEQ;   // 4096
    dim3 gproj(EMB/128, M/128);           // (8, 32)

    gemm_proj<<<gproj, 256>>>(query, Wq, bq, Q, M, EMB, EMB);
    gemm_proj<<<gproj, 256>>>(key,   Wk, bk, K, M, EMB, EMB);
    gemm_proj<<<gproj, 256>>>(value, Wv, bv, V, M, EMB, EMB);

    transpose_k<<<dim3(EMB/32, SEQ/32, BATCH), dim3(32, 8)>>>(V, VT);

    scores_mma<<<dim3(SEQ/128, SEQ/128, BH), 256>>>(Q, K, mask, ATT);

    softmax_avg<<<BATCH*SEQ, 256, SM_SOFT>>>(ATT, attn_avg);

    ctx_mma<<<dim3(SEQ/128, BH), 256>>>(ATT, VT, CTX);

    gemm_proj<<<gproj, 256>>>(CTX, Wo, bo, out, M, EMB, EMB);
}